// round 13
// baseline (speedup 1.0000x reference)
#include <cuda_runtime.h>
#include <cuda_fp16.h>
#include <cstdint>

#define Nn 100000
#define Ee 1600000
#define Hh 64
#define Cc 10
#define Gg 64
#define SORT_SZ (Ee + 3 * Nn + 64)
#define ASTR 72   // smem row stride in halves (conflict-free ldmatrix)

// split point: multiple of 64 (gemm tile) and 16 (agg block): 782*64 = 50048
#define RB    50048
#define G_A   782
#define G_B   781
#define AGG_A (RB / 16)            // 3128 blocks (16 nodes/block)
#define AGG_B ((Nn - RB + 15) / 16)  // 3122 blocks

// ---------------- static device scratch (no allocations allowed) ----------------
__device__ int   d_counts[Nn];
__device__ int   d_cursor[Nn];
__device__ int   d_start[Nn];
__device__ float d_dinv[Nn];
__device__ __align__(16) int d_sorted[SORT_SZ];
__device__ __align__(16) __half2 d_g16[Nn * 32];   // fp16 messages: dinv[row]*(u@W), 128B/row
__device__ float d_h[Nn * Hh];                     // agg output fp32 (layers 1-3)
__device__ __align__(16) __half d_wh[4][64 * 64];  // fp16 weights, k-major [k][n]
__device__ float d_psum[Gg * Hh];
__device__ int   d_gcnt;

// ---------------- prep kernels ----------------
__global__ void k_zero() {
    int i = blockIdx.x * blockDim.x + threadIdx.x;
    if (i < Nn) d_counts[i] = 0;
    if (i < Gg * Hh) d_psum[i] = 0.0f;
    if (i == 0) d_gcnt = 0;
}

__global__ void k_prepw(const float* __restrict__ W1, const float* __restrict__ W2,
                        const float* __restrict__ W3, const float* __restrict__ W4) {
    int i = blockIdx.x * blockDim.x + threadIdx.x;
    if (i < 4096) {
        d_wh[0][i] = __float2half(W1[i]);
        d_wh[1][i] = __float2half(W2[i]);
        d_wh[2][i] = __float2half(W3[i]);
        d_wh[3][i] = __float2half(W4[i]);
    }
}

__global__ void k_count(const int* __restrict__ tgt) {
    int e = blockIdx.x * blockDim.x + threadIdx.x;
    if (e < Ee) atomicAdd(&d_counts[tgt[e]], 1);
}

// Offset allocation, rows padded to 4 ints; also seeds cursor = start.
__global__ void k_start() {
    int tid = threadIdx.x;
    int i = blockIdx.x * 1024 + tid;
    int v  = (i < Nn) ? d_counts[i] : 0;
    int vp = (v + 3) & ~3;
    int lane = tid & 31, wid = tid >> 5;
    int x = vp;
#pragma unroll
    for (int d = 1; d < 32; d <<= 1) {
        int t = __shfl_up_sync(0xffffffffu, x, d);
        if (lane >= d) x += t;
    }
    __shared__ int ws[32];
    __shared__ int sbase;
    if (lane == 31) ws[wid] = x;
    __syncthreads();
    if (wid == 0) {
        int y = ws[lane];
#pragma unroll
        for (int d = 1; d < 32; d <<= 1) {
            int t = __shfl_up_sync(0xffffffffu, y, d);
            if (lane >= d) y += t;
        }
        ws[lane] = y;
    }
    __syncthreads();
    if (tid == 0) sbase = atomicAdd(&d_gcnt, ws[31]);
    __syncthreads();
    int excl = x - vp + (wid ? ws[wid - 1] : 0);
    if (i < Nn) {
        int st = sbase + excl;
        d_start[i]  = st;
        d_cursor[i] = st;
        d_dinv[i]   = rsqrtf(1.0f + (float)v);
    }
}

__global__ void k_fill(const int* __restrict__ src, const int* __restrict__ tgt) {
    int e = blockIdx.x * blockDim.x + threadIdx.x;
    if (e >= Ee) return;
    int pos = atomicAdd(&d_cursor[tgt[e]], 1);
    d_sorted[pos] = src[e];
}

// ---------------- tensor-core GEMM: g16[row] = fp16( dinv[row] * (pre(in[row]) @ W) ) ------
template <bool PRE>
__global__ void __launch_bounds__(128) k_gemm(const float* __restrict__ xin, int widx,
                                              const float* __restrict__ bprev, int row_base) {
    __shared__ __half As[64 * ASTR];
    __shared__ __half Bs[64 * ASTR];
    int tid = threadIdx.x;
    int row0 = row_base + blockIdx.x * 64;
    const float* in = PRE ? d_h : xin;
    const __half* wh = d_wh[widx];

#pragma unroll
    for (int p = 0; p < 4; p++) {
        int idx = tid + p * 128;
        int r = idx >> 3, c8 = idx & 7;
        uint4 v = *(const uint4*)&wh[r * 64 + c8 * 8];
        *(uint4*)&Bs[r * ASTR + c8 * 8] = v;
    }
#pragma unroll
    for (int p = 0; p < 8; p++) {
        int idx = tid + p * 128;
        int r = idx >> 4, c4 = idx & 15;
        int row = row0 + r;
        float4 v = make_float4(0.f, 0.f, 0.f, 0.f);
        if (row < Nn) v = *(const float4*)&in[row * 64 + c4 * 4];
        if (PRE) {
            v.x = fmaxf(v.x + bprev[c4 * 4 + 0], 0.f);
            v.y = fmaxf(v.y + bprev[c4 * 4 + 1], 0.f);
            v.z = fmaxf(v.z + bprev[c4 * 4 + 2], 0.f);
            v.w = fmaxf(v.w + bprev[c4 * 4 + 3], 0.f);
        }
        __half2 h0 = __floats2half2_rn(v.x, v.y);
        __half2 h1 = __floats2half2_rn(v.z, v.w);
        uint2 pk = make_uint2(reinterpret_cast<const unsigned&>(h0),
                              reinterpret_cast<const unsigned&>(h1));
        *(uint2*)&As[r * ASTR + c4 * 4] = pk;
    }
    __syncthreads();

    int warp = tid >> 5, lane = tid & 31;
    int mrow = warp * 16;

    uint32_t a[4][4];
#pragma unroll
    for (int kk = 0; kk < 4; kk++) {
        int r = mrow + (lane & 15);
        int cbyte = kk * 32 + (lane >> 4) * 16;
        uint32_t addr = (uint32_t)__cvta_generic_to_shared(&As[0]) + r * (ASTR * 2) + cbyte;
        asm volatile("ldmatrix.sync.aligned.m8n8.x4.shared.b16 {%0,%1,%2,%3}, [%4];"
                     : "=r"(a[kk][0]), "=r"(a[kk][1]), "=r"(a[kk][2]), "=r"(a[kk][3])
                     : "r"(addr));
    }

    int r0 = row0 + mrow + (lane >> 2);
    int r1 = r0 + 8;
    float dv0 = (r0 < Nn) ? d_dinv[r0] : 0.f;
    float dv1 = (r1 < Nn) ? d_dinv[r1] : 0.f;

#pragma unroll
    for (int n0 = 0; n0 < 64; n0 += 8) {
        float c0 = 0.f, c1 = 0.f, c2 = 0.f, c3 = 0.f;
#pragma unroll
        for (int kk = 0; kk < 4; kk++) {
            int krow = kk * 16 + (lane & 15);
            uint32_t addr = (uint32_t)__cvta_generic_to_shared(&Bs[0])
                          + krow * (ASTR * 2) + n0 * 2;
            uint32_t b0, b1;
            asm volatile("ldmatrix.sync.aligned.m8n8.x2.trans.shared.b16 {%0,%1}, [%2];"
                         : "=r"(b0), "=r"(b1) : "r"(addr));
            asm volatile("mma.sync.aligned.m16n8k16.row.col.f32.f16.f16.f32 "
                         "{%0,%1,%2,%3}, {%4,%5,%6,%7}, {%8,%9}, {%0,%1,%2,%3};"
                         : "+f"(c0), "+f"(c1), "+f"(c2), "+f"(c3)
                         : "r"(a[kk][0]), "r"(a[kk][1]), "r"(a[kk][2]), "r"(a[kk][3]),
                           "r"(b0), "r"(b1));
        }
        int cp = (n0 >> 1) + (lane & 3);
        if (r0 < Nn) {
            __half2 h = __floats2half2_rn(c0 * dv0, c1 * dv0);
            d_g16[r0 * 32 + cp] = h;
        }
        if (r1 < Nn) {
            __half2 h = __floats2half2_rn(c2 * dv1, c3 * dv1);
            d_g16[r1 * 32 + cp] = h;
        }
    }
}

// ---------------- aggregation: h[t] = dinv[t] * (g[t] + sum_{s in N(t)} g[s]) ------------
// 2 nodes/warp, 16 lanes x 8B; int4 index loads. node_base: partition offset (mult of 16).
// POOL: fused mean-pool sum into d_psum (block = 16 contiguous nodes).
template <bool POOL>
__global__ void __launch_bounds__(256) k_agg(const int* __restrict__ batch, int node_base) {
    int w    = (blockIdx.x * blockDim.x + threadIdx.x) >> 5;
    int lane = threadIdx.x & 31;
    int half = lane >> 4;
    int l16  = lane & 15;
    int t = node_base + 2 * w + half;

    float acc0 = 0.f, acc1 = 0.f, acc2 = 0.f, acc3 = 0.f;
    float dv = 0.f;
    if (t < Nn) {
        int base = d_start[t];
        int cnt  = d_counts[t];
        const uint2* __restrict__ g = (const uint2*)d_g16;
        {
            uint2 r = g[t * 16 + l16];
            float2 a = __half22float2(reinterpret_cast<const __half2&>(r.x));
            float2 b = __half22float2(reinterpret_cast<const __half2&>(r.y));
            acc0 = a.x; acc1 = a.y; acc2 = b.x; acc3 = b.y;
        }
        int i = 0;
        for (; i + 8 <= cnt; i += 8) {
            int4 ia = *(const int4*)&d_sorted[base + i];
            int4 ib = *(const int4*)&d_sorted[base + i + 4];
            uint2 r[8];
            r[0] = g[ia.x * 16 + l16];
            r[1] = g[ia.y * 16 + l16];
            r[2] = g[ia.z * 16 + l16];
            r[3] = g[ia.w * 16 + l16];
            r[4] = g[ib.x * 16 + l16];
            r[5] = g[ib.y * 16 + l16];
            r[6] = g[ib.z * 16 + l16];
            r[7] = g[ib.w * 16 + l16];
#pragma unroll
            for (int k = 0; k < 8; k++) {
                float2 a = __half22float2(reinterpret_cast<const __half2&>(r[k].x));
                float2 b = __half22float2(reinterpret_cast<const __half2&>(r[k].y));
                acc0 += a.x; acc1 += a.y; acc2 += b.x; acc3 += b.y;
            }
        }
        int rem = cnt - i;
        if (rem > 0) {
            int4 ia = *(const int4*)&d_sorted[base + i];
            int4 ib = *(const int4*)&d_sorted[base + i + 4];
            int s[8] = {ia.x, ia.y, ia.z, ia.w, ib.x, ib.y, ib.z, ib.w};
#pragma unroll
            for (int k = 0; k < 8; k++) {
                if (k < rem) {
                    uint2 r = g[s[k] * 16 + l16];
                    float2 a = __half22float2(reinterpret_cast<const __half2&>(r.x));
                    float2 b = __half22float2(reinterpret_cast<const __half2&>(r.y));
                    acc0 += a.x; acc1 += a.y; acc2 += b.x; acc3 += b.y;
                }
            }
        }
        dv = d_dinv[t];
    }

    if (!POOL) {
        if (t < Nn) {
            float4 o = make_float4(acc0 * dv, acc1 * dv, acc2 * dv, acc3 * dv);
            *(float4*)&d_h[t * 64 + 4 * l16] = o;
        }
    } else {
        __shared__ float sm_h[16][64];
        __shared__ int   sm_bg[16];
        int nl = (threadIdx.x >> 5) * 2 + half;
        if (t < Nn) {
            sm_h[nl][4 * l16 + 0] = acc0 * dv;
            sm_h[nl][4 * l16 + 1] = acc1 * dv;
            sm_h[nl][4 * l16 + 2] = acc2 * dv;
            sm_h[nl][4 * l16 + 3] = acc3 * dv;
            if (l16 == 0) sm_bg[nl] = batch[t];
        } else if (l16 == 0) sm_bg[nl] = -1;
        __syncthreads();
        if (threadIdx.x < 64) {
            int f = threadIdx.x;
            float acc = 0.f;
            int cur = sm_bg[0];
            for (int n = 0; n < 16; n++) {
                int bg = sm_bg[n];
                if (bg != cur) {
                    if (cur >= 0) atomicAdd(&d_psum[cur * 64 + f], acc);
                    cur = bg; acc = 0.f;
                }
                if (bg >= 0) acc += sm_h[n][f];
            }
            if (cur >= 0) atomicAdd(&d_psum[cur * 64 + f], acc);
        }
    }
}

// ---------------- head: out[g,c] = (psum[g]/cnt[g] + b4) @ Wl + bl ----------------
__global__ void k_final(const int* __restrict__ batch,
                        const float* __restrict__ Wl, const float* __restrict__ bl,
                        const float* __restrict__ b4, float* __restrict__ out) {
    int tid = threadIdx.x;
    if (tid >= Gg * Cc) return;
    int gi = tid / Cc, c = tid % Cc;
    int lo = 0, hi = Nn;
    while (lo < hi) { int m = (lo + hi) >> 1; if (batch[m] < gi) lo = m + 1; else hi = m; }
    int lb = lo; lo = 0; hi = Nn;
    while (lo < hi) { int m = (lo + hi) >> 1; if (batch[m] < gi + 1) lo = m + 1; else hi = m; }
    int cnt = lo - lb;
    float inv = 1.0f / fmaxf((float)cnt, 1.0f);
    float acc = bl[c];
#pragma unroll 8
    for (int k = 0; k < 64; k++) {
        float pooled = d_psum[gi * 64 + k] * inv + b4[k];
        acc = fmaf(pooled, Wl[k * Cc + c], acc);
    }
    out[gi * Cc + c] = acc;
}

// ---------------- launch (dual-stream fork/join) ----------------
extern "C" void kernel_launch(void* const* d_in, const int* in_sizes, int n_in,
                              void* d_out, int out_size) {
    const float* x     = (const float*)d_in[0];
    const int*   ei    = (const int*)d_in[1];
    const int*   batch = (const int*)d_in[2];
    const float* W1 = (const float*)d_in[3],  *b1 = (const float*)d_in[4];
    const float* W2 = (const float*)d_in[5],  *b2 = (const float*)d_in[6];
    const float* W3 = (const float*)d_in[7],  *b3 = (const float*)d_in[8];
    const float* W4 = (const float*)d_in[9],  *b4 = (const float*)d_in[10];
    const float* Wl = (const float*)d_in[11], *bl = (const float*)d_in[12];
    float* out = (float*)d_out;

    const int* src = ei;
    const int* tgt = ei + Ee;
    const float* bp[4] = {nullptr, b1, b2, b3};

    cudaStream_t s2;
    cudaStreamCreateWithFlags(&s2, cudaStreamNonBlocking);
    cudaEvent_t ev[12];
    for (int i = 0; i < 12; i++) cudaEventCreateWithFlags(&ev[i], cudaEventDisableTiming);

    int agg_grid  = (Nn * 16 + 255) / 256;   // 6250 (POOL, full)
    int edge_grid = (Ee + 255) / 256;

    k_zero <<<(Nn + 255) / 256, 256>>>();
    k_prepw<<<16, 256>>>(W1, W2, W3, W4);
    k_count<<<edge_grid, 256>>>(tgt);
    k_start<<<(Nn + 1023) / 1024, 1024>>>();
    cudaEventRecord(ev[0], 0);

    // fork: gemm1 (needs dinv + wh) on s2, concurrent with k_fill on default
    cudaStreamWaitEvent(s2, ev[0], 0);
    k_fill<<<edge_grid, 256>>>(src, tgt);
    k_gemm<false><<<G_A + G_B, 128, 0, s2>>>(x, 0, nullptr, 0);
    cudaEventRecord(ev[1], s2);
    cudaStreamWaitEvent(0, ev[1], 0);

    // layers 1..3: agg(A) -> {gemm+1(A) on s2 || agg(B)} -> gemm+1(B); join
    int e = 2;
    for (int i = 1; i <= 3; i++) {
        k_agg<false><<<AGG_A, 256>>>(nullptr, 0);
        cudaEventRecord(ev[e], 0);
        k_agg<false><<<AGG_B, 256>>>(nullptr, RB);
        cudaEventRecord(ev[e + 1], 0);
        cudaStreamWaitEvent(s2, ev[e], 0);
        k_gemm<true><<<G_A, 128, 0, s2>>>(nullptr, i, bp[i], 0);
        cudaStreamWaitEvent(s2, ev[e + 1], 0);
        k_gemm<true><<<G_B, 128, 0, s2>>>(nullptr, i, bp[i], RB);
        cudaEventRecord(ev[e + 2], s2);
        cudaStreamWaitEvent(0, ev[e + 2], 0);
        e += 3;
    }

    k_agg<true><<<agg_grid, 256>>>(batch, 0);   // fused mean-pool
    k_final<<<1, Gg * Cc>>>(batch, Wl, bl, b4, out);
}

// round 14
// speedup vs baseline: 1.1262x; 1.1262x over previous
#include <cuda_runtime.h>
#include <cuda_fp16.h>
#include <cstdint>

#define Nn 100000
#define Ee 1600000
#define Hh 64
#define Cc 10
#define Gg 64
#define SORT_SZ (Ee + 3 * Nn + 64)
#define ASTR 72   // smem row stride in halves (conflict-free ldmatrix)

// ---------------- static device scratch (no allocations allowed) ----------------
__device__ int   d_counts[Nn];
__device__ int   d_cursor[Nn];
__device__ int   d_start[Nn];
__device__ float d_dinv[Nn];
__device__ __align__(16) int d_sorted[SORT_SZ];
__device__ __align__(16) __half2 d_g16[Nn * 32];   // fp16 messages: dinv[row]*(u@W), 128B/row
__device__ __align__(16) __half2 d_h16[Nn * 32];   // fp16 hidden state (layers 1-3 agg out)
__device__ __align__(16) __half d_wh[4][64 * 64];  // fp16 weights, k-major [k][n]
__device__ float d_psum[Gg * Hh];
__device__ int   d_gcnt;

// ---------------- prep: zero + weight convert in one launch ----------------
__global__ void k_init(const float* __restrict__ W1, const float* __restrict__ W2,
                       const float* __restrict__ W3, const float* __restrict__ W4) {
    int i = blockIdx.x * blockDim.x + threadIdx.x;
    if (i < Nn) d_counts[i] = 0;
    if (i < Gg * Hh) d_psum[i] = 0.0f;
    if (i == 0) d_gcnt = 0;
    if (i < 4096) {
        d_wh[0][i] = __float2half(W1[i]);
        d_wh[1][i] = __float2half(W2[i]);
        d_wh[2][i] = __float2half(W3[i]);
        d_wh[3][i] = __float2half(W4[i]);
    }
}

__global__ void k_count(const int* __restrict__ tgt) {
    int e = blockIdx.x * blockDim.x + threadIdx.x;
    if (e < Ee) atomicAdd(&d_counts[tgt[e]], 1);
}

// Offset allocation, rows padded to 4 ints; also seeds cursor = start.
__global__ void k_start() {
    int tid = threadIdx.x;
    int i = blockIdx.x * 1024 + tid;
    int v  = (i < Nn) ? d_counts[i] : 0;
    int vp = (v + 3) & ~3;
    int lane = tid & 31, wid = tid >> 5;
    int x = vp;
#pragma unroll
    for (int d = 1; d < 32; d <<= 1) {
        int t = __shfl_up_sync(0xffffffffu, x, d);
        if (lane >= d) x += t;
    }
    __shared__ int ws[32];
    __shared__ int sbase;
    if (lane == 31) ws[wid] = x;
    __syncthreads();
    if (wid == 0) {
        int y = ws[lane];
#pragma unroll
        for (int d = 1; d < 32; d <<= 1) {
            int t = __shfl_up_sync(0xffffffffu, y, d);
            if (lane >= d) y += t;
        }
        ws[lane] = y;
    }
    __syncthreads();
    if (tid == 0) sbase = atomicAdd(&d_gcnt, ws[31]);
    __syncthreads();
    int excl = x - vp + (wid ? ws[wid - 1] : 0);
    if (i < Nn) {
        int st = sbase + excl;
        d_start[i]  = st;
        d_cursor[i] = st;
        d_dinv[i]   = rsqrtf(1.0f + (float)v);
    }
}

__global__ void k_fill(const int* __restrict__ src, const int* __restrict__ tgt) {
    int e = blockIdx.x * blockDim.x + threadIdx.x;
    if (e >= Ee) return;
    int pos = atomicAdd(&d_cursor[tgt[e]], 1);
    d_sorted[pos] = src[e];
}

// ---------------- tensor-core GEMM: g16[row] = fp16( dinv[row] * (pre(in[row]) @ W) ) ------
// PRE=false: in = x (fp32). PRE=true: in = d_h16 (fp16), pre(v) = relu(v + bprev) in fp32.
template <bool PRE>
__global__ void __launch_bounds__(128) k_gemm(const float* __restrict__ xin, int widx,
                                              const float* __restrict__ bprev) {
    __shared__ __half As[64 * ASTR];
    __shared__ __half Bs[64 * ASTR];
    int tid = threadIdx.x;
    int row0 = blockIdx.x * 64;
    const __half* wh = d_wh[widx];

#pragma unroll
    for (int p = 0; p < 4; p++) {
        int idx = tid + p * 128;
        int r = idx >> 3, c8 = idx & 7;
        uint4 v = *(const uint4*)&wh[r * 64 + c8 * 8];
        *(uint4*)&Bs[r * ASTR + c8 * 8] = v;
    }
#pragma unroll
    for (int p = 0; p < 8; p++) {
        int idx = tid + p * 128;
        int r = idx >> 4, c4 = idx & 15;
        int row = row0 + r;
        float4 v = make_float4(0.f, 0.f, 0.f, 0.f);
        if (row < Nn) {
            if (PRE) {
                uint2 pv = *(const uint2*)&d_h16[row * 32 + c4 * 2];
                float2 f0 = __half22float2(reinterpret_cast<const __half2&>(pv.x));
                float2 f1 = __half22float2(reinterpret_cast<const __half2&>(pv.y));
                v = make_float4(f0.x, f0.y, f1.x, f1.y);
            } else {
                v = *(const float4*)&xin[row * 64 + c4 * 4];
            }
        }
        if (PRE) {
            v.x = fmaxf(v.x + bprev[c4 * 4 + 0], 0.f);
            v.y = fmaxf(v.y + bprev[c4 * 4 + 1], 0.f);
            v.z = fmaxf(v.z + bprev[c4 * 4 + 2], 0.f);
            v.w = fmaxf(v.w + bprev[c4 * 4 + 3], 0.f);
        }
        __half2 h0 = __floats2half2_rn(v.x, v.y);
        __half2 h1 = __floats2half2_rn(v.z, v.w);
        uint2 pk = make_uint2(reinterpret_cast<const unsigned&>(h0),
                              reinterpret_cast<const unsigned&>(h1));
        *(uint2*)&As[r * ASTR + c4 * 4] = pk;
    }
    __syncthreads();

    int warp = tid >> 5, lane = tid & 31;
    int mrow = warp * 16;

    uint32_t a[4][4];
#pragma unroll
    for (int kk = 0; kk < 4; kk++) {
        int r = mrow + (lane & 15);
        int cbyte = kk * 32 + (lane >> 4) * 16;
        uint32_t addr = (uint32_t)__cvta_generic_to_shared(&As[0]) + r * (ASTR * 2) + cbyte;
        asm volatile("ldmatrix.sync.aligned.m8n8.x4.shared.b16 {%0,%1,%2,%3}, [%4];"
                     : "=r"(a[kk][0]), "=r"(a[kk][1]), "=r"(a[kk][2]), "=r"(a[kk][3])
                     : "r"(addr));
    }

    int r0 = row0 + mrow + (lane >> 2);
    int r1 = r0 + 8;
    float dv0 = (r0 < Nn) ? d_dinv[r0] : 0.f;
    float dv1 = (r1 < Nn) ? d_dinv[r1] : 0.f;

#pragma unroll
    for (int n0 = 0; n0 < 64; n0 += 8) {
        float c0 = 0.f, c1 = 0.f, c2 = 0.f, c3 = 0.f;
#pragma unroll
        for (int kk = 0; kk < 4; kk++) {
            int krow = kk * 16 + (lane & 15);
            uint32_t addr = (uint32_t)__cvta_generic_to_shared(&Bs[0])
                          + krow * (ASTR * 2) + n0 * 2;
            uint32_t b0, b1;
            asm volatile("ldmatrix.sync.aligned.m8n8.x2.trans.shared.b16 {%0,%1}, [%2];"
                         : "=r"(b0), "=r"(b1) : "r"(addr));
            asm volatile("mma.sync.aligned.m16n8k16.row.col.f32.f16.f16.f32 "
                         "{%0,%1,%2,%3}, {%4,%5,%6,%7}, {%8,%9}, {%0,%1,%2,%3};"
                         : "+f"(c0), "+f"(c1), "+f"(c2), "+f"(c3)
                         : "r"(a[kk][0]), "r"(a[kk][1]), "r"(a[kk][2]), "r"(a[kk][3]),
                           "r"(b0), "r"(b1));
        }
        int cp = (n0 >> 1) + (lane & 3);
        if (r0 < Nn) {
            __half2 h = __floats2half2_rn(c0 * dv0, c1 * dv0);
            d_g16[r0 * 32 + cp] = h;
        }
        if (r1 < Nn) {
            __half2 h = __floats2half2_rn(c2 * dv1, c3 * dv1);
            d_g16[r1 * 32 + cp] = h;
        }
    }
}

// ---------------- aggregation: h[t] = dinv[t] * (g[t] + sum_{s in N(t)} g[s]) ------------
// 2 nodes/warp, 16 lanes x 8B; int4 index loads. Non-POOL writes fp16 d_h16;
// POOL: fused mean-pool sum into d_psum (block = 16 contiguous nodes).
template <bool POOL>
__global__ void __launch_bounds__(256) k_agg(const int* __restrict__ batch) {
    int w    = (blockIdx.x * blockDim.x + threadIdx.x) >> 5;
    int lane = threadIdx.x & 31;
    int half = lane >> 4;
    int l16  = lane & 15;
    int t = 2 * w + half;

    float acc0 = 0.f, acc1 = 0.f, acc2 = 0.f, acc3 = 0.f;
    float dv = 0.f;
    if (t < Nn) {
        int base = d_start[t];
        int cnt  = d_counts[t];
        const uint2* __restrict__ g = (const uint2*)d_g16;
        {
            uint2 r = g[t * 16 + l16];
            float2 a = __half22float2(reinterpret_cast<const __half2&>(r.x));
            float2 b = __half22float2(reinterpret_cast<const __half2&>(r.y));
            acc0 = a.x; acc1 = a.y; acc2 = b.x; acc3 = b.y;
        }
        int i = 0;
        for (; i + 8 <= cnt; i += 8) {
            int4 ia = *(const int4*)&d_sorted[base + i];
            int4 ib = *(const int4*)&d_sorted[base + i + 4];
            uint2 r[8];
            r[0] = g[ia.x * 16 + l16];
            r[1] = g[ia.y * 16 + l16];
            r[2] = g[ia.z * 16 + l16];
            r[3] = g[ia.w * 16 + l16];
            r[4] = g[ib.x * 16 + l16];
            r[5] = g[ib.y * 16 + l16];
            r[6] = g[ib.z * 16 + l16];
            r[7] = g[ib.w * 16 + l16];
#pragma unroll
            for (int k = 0; k < 8; k++) {
                float2 a = __half22float2(reinterpret_cast<const __half2&>(r[k].x));
                float2 b = __half22float2(reinterpret_cast<const __half2&>(r[k].y));
                acc0 += a.x; acc1 += a.y; acc2 += b.x; acc3 += b.y;
            }
        }
        int rem = cnt - i;
        if (rem > 0) {
            int4 ia = *(const int4*)&d_sorted[base + i];
            int4 ib = *(const int4*)&d_sorted[base + i + 4];
            int s[8] = {ia.x, ia.y, ia.z, ia.w, ib.x, ib.y, ib.z, ib.w};
#pragma unroll
            for (int k = 0; k < 8; k++) {
                if (k < rem) {
                    uint2 r = g[s[k] * 16 + l16];
                    float2 a = __half22float2(reinterpret_cast<const __half2&>(r.x));
                    float2 b = __half22float2(reinterpret_cast<const __half2&>(r.y));
                    acc0 += a.x; acc1 += a.y; acc2 += b.x; acc3 += b.y;
                }
            }
        }
        dv = d_dinv[t];
    }

    if (!POOL) {
        if (t < Nn) {
            __half2 h0 = __floats2half2_rn(acc0 * dv, acc1 * dv);
            __half2 h1 = __floats2half2_rn(acc2 * dv, acc3 * dv);
            uint2 pk = make_uint2(reinterpret_cast<const unsigned&>(h0),
                                  reinterpret_cast<const unsigned&>(h1));
            *(uint2*)&d_h16[t * 32 + 2 * l16] = pk;
        }
    } else {
        __shared__ float sm_h[16][64];
        __shared__ int   sm_bg[16];
        int nl = (threadIdx.x >> 5) * 2 + half;
        if (t < Nn) {
            sm_h[nl][4 * l16 + 0] = acc0 * dv;
            sm_h[nl][4 * l16 + 1] = acc1 * dv;
            sm_h[nl][4 * l16 + 2] = acc2 * dv;
            sm_h[nl][4 * l16 + 3] = acc3 * dv;
            if (l16 == 0) sm_bg[nl] = batch[t];
        } else if (l16 == 0) sm_bg[nl] = -1;
        __syncthreads();
        if (threadIdx.x < 64) {
            int f = threadIdx.x;
            float acc = 0.f;
            int cur = sm_bg[0];
            for (int n = 0; n < 16; n++) {
                int bg = sm_bg[n];
                if (bg != cur) {
                    if (cur >= 0) atomicAdd(&d_psum[cur * 64 + f], acc);
                    cur = bg; acc = 0.f;
                }
                if (bg >= 0) acc += sm_h[n][f];
            }
            if (cur >= 0) atomicAdd(&d_psum[cur * 64 + f], acc);
        }
    }
}

// ---------------- head: out[g,c] = (psum[g]/cnt[g] + b4) @ Wl + bl ----------------
__global__ void k_final(const int* __restrict__ batch,
                        const float* __restrict__ Wl, const float* __restrict__ bl,
                        const float* __restrict__ b4, float* __restrict__ out) {
    int tid = threadIdx.x;
    if (tid >= Gg * Cc) return;
    int gi = tid / Cc, c = tid % Cc;
    int lo = 0, hi = Nn;
    while (lo < hi) { int m = (lo + hi) >> 1; if (batch[m] < gi) lo = m + 1; else hi = m; }
    int lb = lo; lo = 0; hi = Nn;
    while (lo < hi) { int m = (lo + hi) >> 1; if (batch[m] < gi + 1) lo = m + 1; else hi = m; }
    int cnt = lo - lb;
    float inv = 1.0f / fmaxf((float)cnt, 1.0f);
    float acc = bl[c];
#pragma unroll 8
    for (int k = 0; k < 64; k++) {
        float pooled = d_psum[gi * 64 + k] * inv + b4[k];
        acc = fmaf(pooled, Wl[k * Cc + c], acc);
    }
    out[gi * Cc + c] = acc;
}

// ---------------- launch (single stream — R13 dual-stream regressed) ----------------
extern "C" void kernel_launch(void* const* d_in, const int* in_sizes, int n_in,
                              void* d_out, int out_size) {
    const float* x     = (const float*)d_in[0];
    const int*   ei    = (const int*)d_in[1];
    const int*   batch = (const int*)d_in[2];
    const float* W1 = (const float*)d_in[3],  *b1 = (const float*)d_in[4];
    const float* W2 = (const float*)d_in[5],  *b2 = (const float*)d_in[6];
    const float* W3 = (const float*)d_in[7],  *b3 = (const float*)d_in[8];
    const float* W4 = (const float*)d_in[9],  *b4 = (const float*)d_in[10];
    const float* Wl = (const float*)d_in[11], *bl = (const float*)d_in[12];
    float* out = (float*)d_out;

    const int* src = ei;
    const int* tgt = ei + Ee;

    int gemm_grid = (Nn + 63) / 64;
    int agg_grid  = (Nn * 16 + 255) / 256;
    int edge_grid = (Ee + 255) / 256;

    k_init <<<(Nn + 255) / 256, 256>>>(W1, W2, W3, W4);
    k_count<<<edge_grid, 256>>>(tgt);
    k_start<<<(Nn + 1023) / 1024, 1024>>>();
    k_gemm<false><<<gemm_grid, 128>>>(x, 0, nullptr);
    k_fill <<<edge_grid, 256>>>(src, tgt);

    k_agg<false><<<agg_grid, 256>>>(nullptr);
    k_gemm<true><<<gemm_grid, 128>>>(nullptr, 1, b1);
    k_agg<false><<<agg_grid, 256>>>(nullptr);
    k_gemm<true><<<gemm_grid, 128>>>(nullptr, 2, b2);
    k_agg<false><<<agg_grid, 256>>>(nullptr);
    k_gemm<true><<<gemm_grid, 128>>>(nullptr, 3, b3);
    k_agg<true><<<agg_grid, 256>>>(batch);

    k_final<<<1, Gg * Cc>>>(batch, Wl, bl, b4, out);
}

// round 15
// speedup vs baseline: 1.1341x; 1.0070x over previous
#include <cuda_runtime.h>
#include <cuda_fp16.h>
#include <cstdint>

#define Nn 100000
#define Ee 1600000
#define Hh 64
#define Cc 10
#define Gg 64
#define SORT_SZ (Ee + 3 * Nn + 64)
#define ASTR 72          // smem row stride in halves (conflict-free ldmatrix)
#define WARM_BLOCKS 391  // 391*256 threads x 16 float4 = 25.6MB = all of x

// ---------------- static device scratch (no allocations allowed) ----------------
__device__ int   d_counts[Nn];
__device__ int   d_cursor[Nn];
__device__ int   d_start[Nn];
__device__ float d_dinv[Nn];
__device__ __align__(16) int d_sorted[SORT_SZ];
__device__ __align__(16) __half2 d_g16[Nn * 32];   // fp16 messages: dinv[row]*(u@W), 128B/row
__device__ __align__(16) __half2 d_h16[Nn * 32];   // fp16 hidden state (layers 1-3 agg out)
__device__ __align__(16) __half d_wh[4][64 * 64];  // fp16 weights, k-major [k][n]
__device__ float d_psum[Gg * Hh];
__device__ float d_sink;                           // L2-warm keep-alive sink
__device__ int   d_gcnt;

// ---------------- prep: zero + weight convert in one launch ----------------
__global__ void k_init(const float* __restrict__ W1, const float* __restrict__ W2,
                       const float* __restrict__ W3, const float* __restrict__ W4) {
    int i = blockIdx.x * blockDim.x + threadIdx.x;
    if (i < Nn) d_counts[i] = 0;
    if (i < Gg * Hh) d_psum[i] = 0.0f;
    if (i == 0) d_gcnt = 0;
    if (i < 4096) {
        d_wh[0][i] = __float2half(W1[i]);
        d_wh[1][i] = __float2half(W2[i]);
        d_wh[2][i] = __float2half(W3[i]);
        d_wh[3][i] = __float2half(W4[i]);
    }
}

// counting + x L2-warm in one grid. Warm blocks FIRST so they stream x
// while the (latency-bound, low-BW) atomic counting blocks run.
__global__ void k_count(const int* __restrict__ tgt, const float* __restrict__ x) {
    int b = blockIdx.x;
    if (b < WARM_BLOCKS) {
        const float4* __restrict__ x4 = (const float4*)x;
        int i = b * 256 + threadIdx.x;               // 0..100095
        float s = 0.f;
#pragma unroll
        for (int k = 0; k < 16; k++) {
            int idx = i + k * (WARM_BLOCKS * 256);
            if (idx < Nn * 16) {
                float4 v = x4[idx];
                s += v.x + v.y + v.z + v.w;
            }
        }
        if (s < -1e30f) d_sink = s;                  // never true for finite inputs
    } else {
        int e = (b - WARM_BLOCKS) * 256 + threadIdx.x;
        if (e < Ee) atomicAdd(&d_counts[tgt[e]], 1);
    }
}

// Offset allocation, rows padded to 4 ints; also seeds cursor = start.
__global__ void k_start() {
    int tid = threadIdx.x;
    int i = blockIdx.x * 1024 + tid;
    int v  = (i < Nn) ? d_counts[i] : 0;
    int vp = (v + 3) & ~3;
    int lane = tid & 31, wid = tid >> 5;
    int x = vp;
#pragma unroll
    for (int d = 1; d < 32; d <<= 1) {
        int t = __shfl_up_sync(0xffffffffu, x, d);
        if (lane >= d) x += t;
    }
    __shared__ int ws[32];
    __shared__ int sbase;
    if (lane == 31) ws[wid] = x;
    __syncthreads();
    if (wid == 0) {
        int y = ws[lane];
#pragma unroll
        for (int d = 1; d < 32; d <<= 1) {
            int t = __shfl_up_sync(0xffffffffu, y, d);
            if (lane >= d) y += t;
        }
        ws[lane] = y;
    }
    __syncthreads();
    if (tid == 0) sbase = atomicAdd(&d_gcnt, ws[31]);
    __syncthreads();
    int excl = x - vp + (wid ? ws[wid - 1] : 0);
    if (i < Nn) {
        int st = sbase + excl;
        d_start[i]  = st;
        d_cursor[i] = st;
        d_dinv[i]   = rsqrtf(1.0f + (float)v);
    }
}

// 2 independent atomic+store chains per thread at full occupancy (800k threads)
__global__ void k_fill(const int* __restrict__ src, const int* __restrict__ tgt) {
    int e = blockIdx.x * blockDim.x + threadIdx.x;
    if (e >= Ee / 2) return;
    int e2 = e + Ee / 2;
    int t0 = tgt[e], t1 = tgt[e2];
    int p0 = atomicAdd(&d_cursor[t0], 1);
    int p1 = atomicAdd(&d_cursor[t1], 1);
    d_sorted[p0] = src[e];
    d_sorted[p1] = src[e2];
}

// ---------------- tensor-core GEMM: g16[row] = fp16( dinv[row] * (pre(in[row]) @ W) ) ------
// PRE=false: in = x (fp32). PRE=true: in = d_h16 (fp16), pre(v) = relu(v + bprev) in fp32.
template <bool PRE>
__global__ void __launch_bounds__(128) k_gemm(const float* __restrict__ xin, int widx,
                                              const float* __restrict__ bprev) {
    __shared__ __half As[64 * ASTR];
    __shared__ __half Bs[64 * ASTR];
    int tid = threadIdx.x;
    int row0 = blockIdx.x * 64;
    const __half* wh = d_wh[widx];

#pragma unroll
    for (int p = 0; p < 4; p++) {
        int idx = tid + p * 128;
        int r = idx >> 3, c8 = idx & 7;
        uint4 v = *(const uint4*)&wh[r * 64 + c8 * 8];
        *(uint4*)&Bs[r * ASTR + c8 * 8] = v;
    }
#pragma unroll
    for (int p = 0; p < 8; p++) {
        int idx = tid + p * 128;
        int r = idx >> 4, c4 = idx & 15;
        int row = row0 + r;
        float4 v = make_float4(0.f, 0.f, 0.f, 0.f);
        if (row < Nn) {
            if (PRE) {
                uint2 pv = *(const uint2*)&d_h16[row * 32 + c4 * 2];
                float2 f0 = __half22float2(reinterpret_cast<const __half2&>(pv.x));
                float2 f1 = __half22float2(reinterpret_cast<const __half2&>(pv.y));
                v = make_float4(f0.x, f0.y, f1.x, f1.y);
            } else {
                v = *(const float4*)&xin[row * 64 + c4 * 4];
            }
        }
        if (PRE) {
            v.x = fmaxf(v.x + bprev[c4 * 4 + 0], 0.f);
            v.y = fmaxf(v.y + bprev[c4 * 4 + 1], 0.f);
            v.z = fmaxf(v.z + bprev[c4 * 4 + 2], 0.f);
            v.w = fmaxf(v.w + bprev[c4 * 4 + 3], 0.f);
        }
        __half2 h0 = __floats2half2_rn(v.x, v.y);
        __half2 h1 = __floats2half2_rn(v.z, v.w);
        uint2 pk = make_uint2(reinterpret_cast<const unsigned&>(h0),
                              reinterpret_cast<const unsigned&>(h1));
        *(uint2*)&As[r * ASTR + c4 * 4] = pk;
    }
    __syncthreads();

    int warp = tid >> 5, lane = tid & 31;
    int mrow = warp * 16;

    uint32_t a[4][4];
#pragma unroll
    for (int kk = 0; kk < 4; kk++) {
        int r = mrow + (lane & 15);
        int cbyte = kk * 32 + (lane >> 4) * 16;
        uint32_t addr = (uint32_t)__cvta_generic_to_shared(&As[0]) + r * (ASTR * 2) + cbyte;
        asm volatile("ldmatrix.sync.aligned.m8n8.x4.shared.b16 {%0,%1,%2,%3}, [%4];"
                     : "=r"(a[kk][0]), "=r"(a[kk][1]), "=r"(a[kk][2]), "=r"(a[kk][3])
                     : "r"(addr));
    }

    int r0 = row0 + mrow + (lane >> 2);
    int r1 = r0 + 8;
    float dv0 = (r0 < Nn) ? d_dinv[r0] : 0.f;
    float dv1 = (r1 < Nn) ? d_dinv[r1] : 0.f;

#pragma unroll
    for (int n0 = 0; n0 < 64; n0 += 8) {
        float c0 = 0.f, c1 = 0.f, c2 = 0.f, c3 = 0.f;
#pragma unroll
        for (int kk = 0; kk < 4; kk++) {
            int krow = kk * 16 + (lane & 15);
            uint32_t addr = (uint32_t)__cvta_generic_to_shared(&Bs[0])
                          + krow * (ASTR * 2) + n0 * 2;
            uint32_t b0, b1;
            asm volatile("ldmatrix.sync.aligned.m8n8.x2.trans.shared.b16 {%0,%1}, [%2];"
                         : "=r"(b0), "=r"(b1) : "r"(addr));
            asm volatile("mma.sync.aligned.m16n8k16.row.col.f32.f16.f16.f32 "
                         "{%0,%1,%2,%3}, {%4,%5,%6,%7}, {%8,%9}, {%0,%1,%2,%3};"
                         : "+f"(c0), "+f"(c1), "+f"(c2), "+f"(c3)
                         : "r"(a[kk][0]), "r"(a[kk][1]), "r"(a[kk][2]), "r"(a[kk][3]),
                           "r"(b0), "r"(b1));
        }
        int cp = (n0 >> 1) + (lane & 3);
        if (r0 < Nn) {
            __half2 h = __floats2half2_rn(c0 * dv0, c1 * dv0);
            d_g16[r0 * 32 + cp] = h;
        }
        if (r1 < Nn) {
            __half2 h = __floats2half2_rn(c2 * dv1, c3 * dv1);
            d_g16[r1 * 32 + cp] = h;
        }
    }
}

// ---------------- aggregation: h[t] = dinv[t] * (g[t] + sum_{s in N(t)} g[s]) ------------
template <bool POOL>
__global__ void __launch_bounds__(256) k_agg(const int* __restrict__ batch) {
    int w    = (blockIdx.x * blockDim.x + threadIdx.x) >> 5;
    int lane = threadIdx.x & 31;
    int half = lane >> 4;
    int l16  = lane & 15;
    int t = 2 * w + half;

    float acc0 = 0.f, acc1 = 0.f, acc2 = 0.f, acc3 = 0.f;
    float dv = 0.f;
    if (t < Nn) {
        int base = d_start[t];
        int cnt  = d_counts[t];
        const uint2* __restrict__ g = (const uint2*)d_g16;
        {
            uint2 r = g[t * 16 + l16];
            float2 a = __half22float2(reinterpret_cast<const __half2&>(r.x));
            float2 b = __half22float2(reinterpret_cast<const __half2&>(r.y));
            acc0 = a.x; acc1 = a.y; acc2 = b.x; acc3 = b.y;
        }
        int i = 0;
        for (; i + 8 <= cnt; i += 8) {
            int4 ia = *(const int4*)&d_sorted[base + i];
            int4 ib = *(const int4*)&d_sorted[base + i + 4];
            uint2 r[8];
            r[0] = g[ia.x * 16 + l16];
            r[1] = g[ia.y * 16 + l16];
            r[2] = g[ia.z * 16 + l16];
            r[3] = g[ia.w * 16 + l16];
            r[4] = g[ib.x * 16 + l16];
            r[5] = g[ib.y * 16 + l16];
            r[6] = g[ib.z * 16 + l16];
            r[7] = g[ib.w * 16 + l16];
#pragma unroll
            for (int k = 0; k < 8; k++) {
                float2 a = __half22float2(reinterpret_cast<const __half2&>(r[k].x));
                float2 b = __half22float2(reinterpret_cast<const __half2&>(r[k].y));
                acc0 += a.x; acc1 += a.y; acc2 += b.x; acc3 += b.y;
            }
        }
        int rem = cnt - i;
        if (rem > 0) {
            int4 ia = *(const int4*)&d_sorted[base + i];
            int4 ib = *(const int4*)&d_sorted[base + i + 4];
            int s[8] = {ia.x, ia.y, ia.z, ia.w, ib.x, ib.y, ib.z, ib.w};
#pragma unroll
            for (int k = 0; k < 8; k++) {
                if (k < rem) {
                    uint2 r = g[s[k] * 16 + l16];
                    float2 a = __half22float2(reinterpret_cast<const __half2&>(r.x));
                    float2 b = __half22float2(reinterpret_cast<const __half2&>(r.y));
                    acc0 += a.x; acc1 += a.y; acc2 += b.x; acc3 += b.y;
                }
            }
        }
        dv = d_dinv[t];
    }

    if (!POOL) {
        if (t < Nn) {
            __half2 h0 = __floats2half2_rn(acc0 * dv, acc1 * dv);
            __half2 h1 = __floats2half2_rn(acc2 * dv, acc3 * dv);
            uint2 pk = make_uint2(reinterpret_cast<const unsigned&>(h0),
                                  reinterpret_cast<const unsigned&>(h1));
            *(uint2*)&d_h16[t * 32 + 2 * l16] = pk;
        }
    } else {
        __shared__ float sm_h[16][64];
        __shared__ int   sm_bg[16];
        int nl = (threadIdx.x >> 5) * 2 + half;
        if (t < Nn) {
            sm_h[nl][4 * l16 + 0] = acc0 * dv;
            sm_h[nl][4 * l16 + 1] = acc1 * dv;
            sm_h[nl][4 * l16 + 2] = acc2 * dv;
            sm_h[nl][4 * l16 + 3] = acc3 * dv;
            if (l16 == 0) sm_bg[nl] = batch[t];
        } else if (l16 == 0) sm_bg[nl] = -1;
        __syncthreads();
        if (threadIdx.x < 64) {
            int f = threadIdx.x;
            float acc = 0.f;
            int cur = sm_bg[0];
            for (int n = 0; n < 16; n++) {
                int bg = sm_bg[n];
                if (bg != cur) {
                    if (cur >= 0) atomicAdd(&d_psum[cur * 64 + f], acc);
                    cur = bg; acc = 0.f;
                }
                if (bg >= 0) acc += sm_h[n][f];
            }
            if (cur >= 0) atomicAdd(&d_psum[cur * 64 + f], acc);
        }
    }
}

// ---------------- head: out[g,c] = (psum[g]/cnt[g] + b4) @ Wl + bl ----------------
__global__ void k_final(const int* __restrict__ batch,
                        const float* __restrict__ Wl, const float* __restrict__ bl,
                        const float* __restrict__ b4, float* __restrict__ out) {
    int tid = threadIdx.x;
    if (tid >= Gg * Cc) return;
    int gi = tid / Cc, c = tid % Cc;
    int lo = 0, hi = Nn;
    while (lo < hi) { int m = (lo + hi) >> 1; if (batch[m] < gi) lo = m + 1; else hi = m; }
    int lb = lo; lo = 0; hi = Nn;
    while (lo < hi) { int m = (lo + hi) >> 1; if (batch[m] < gi + 1) lo = m + 1; else hi = m; }
    int cnt = lo - lb;
    float inv = 1.0f / fmaxf((float)cnt, 1.0f);
    float acc = bl[c];
#pragma unroll 8
    for (int k = 0; k < 64; k++) {
        float pooled = d_psum[gi * 64 + k] * inv + b4[k];
        acc = fmaf(pooled, Wl[k * Cc + c], acc);
    }
    out[gi * Cc + c] = acc;
}

// ---------------- launch ----------------
extern "C" void kernel_launch(void* const* d_in, const int* in_sizes, int n_in,
                              void* d_out, int out_size) {
    const float* x     = (const float*)d_in[0];
    const int*   ei    = (const int*)d_in[1];
    const int*   batch = (const int*)d_in[2];
    const float* W1 = (const float*)d_in[3],  *b1 = (const float*)d_in[4];
    const float* W2 = (const float*)d_in[5],  *b2 = (const float*)d_in[6];
    const float* W3 = (const float*)d_in[7],  *b3 = (const float*)d_in[8];
    const float* W4 = (const float*)d_in[9],  *b4 = (const float*)d_in[10];
    const float* Wl = (const float*)d_in[11], *bl = (const float*)d_in[12];
    float* out = (float*)d_out;

    const int* src = ei;
    const int* tgt = ei + Ee;

    int gemm_grid = (Nn + 63) / 64;
    int agg_grid  = (Nn * 16 + 255) / 256;
    int edge_grid = (Ee + 255) / 256;

    k_init <<<(Nn + 255) / 256, 256>>>(W1, W2, W3, W4);
    k_count<<<WARM_BLOCKS + edge_grid, 256>>>(tgt, x);
    k_start<<<(Nn + 1023) / 1024, 1024>>>();
    k_gemm<false><<<gemm_grid, 128>>>(x, 0, nullptr);
    k_fill <<<(Ee / 2 + 255) / 256, 256>>>(src, tgt);

    k_agg<false><<<agg_grid, 256>>>(nullptr);
    k_gemm<true><<<gemm_grid, 128>>>(nullptr, 1, b1);
    k_agg<false><<<agg_grid, 256>>>(nullptr);
    k_gemm<true><<<gemm_grid, 128>>>(nullptr, 2, b2);
    k_agg<false><<<agg_grid, 256>>>(nullptr);
    k_gemm<true><<<gemm_grid, 128>>>(nullptr, 3, b3);
    k_agg<true><<<agg_grid, 256>>>(batch);

    k_final<<<1, Gg * Cc>>>(batch, Wl, bl, b4, out);
}

// round 16
// speedup vs baseline: 1.1467x; 1.0111x over previous
#include <cuda_runtime.h>
#include <cuda_fp16.h>
#include <cstdint>

#define Nn 100000
#define Ee 1600000
#define Hh 64
#define Cc 10
#define Gg 64
#define SORT_SZ (Ee + 3 * Nn + 64)
#define ASTR 72          // smem row stride in halves (conflict-free ldmatrix)
#define WARM_BLOCKS 391  // warm x into L2 under k_count's latency shadow

// ---------------- static device scratch (no allocations allowed) ----------------
__device__ int   d_counts[Nn];
__device__ int   d_cursor[Nn];
__device__ int   d_start[Nn];
__device__ float d_dinv[Nn];
__device__ __align__(16) int d_sorted[SORT_SZ];
__device__ __align__(16) __half2 d_gbuf[2][Nn * 32]; // double-buffered fp16 messages, 128B/row
__device__ __align__(16) __half d_wh[4][64 * 64];    // fp16 weights, k-major [k][n]
__device__ float d_psum[Gg * Hh];
__device__ float d_sink;
__device__ int   d_gcnt;

// ---------------- prep: zero + weight convert in one launch ----------------
__global__ void k_init(const float* __restrict__ W1, const float* __restrict__ W2,
                       const float* __restrict__ W3, const float* __restrict__ W4) {
    int i = blockIdx.x * blockDim.x + threadIdx.x;
    if (i < Nn) d_counts[i] = 0;
    if (i < Gg * Hh) d_psum[i] = 0.0f;
    if (i == 0) d_gcnt = 0;
    if (i < 4096) {
        d_wh[0][i] = __float2half(W1[i]);
        d_wh[1][i] = __float2half(W2[i]);
        d_wh[2][i] = __float2half(W3[i]);
        d_wh[3][i] = __float2half(W4[i]);
    }
}

// counting + x L2-warm in one grid
__global__ void k_count(const int* __restrict__ tgt, const float* __restrict__ x) {
    int b = blockIdx.x;
    if (b < WARM_BLOCKS) {
        const float4* __restrict__ x4 = (const float4*)x;
        int i = b * 256 + threadIdx.x;
        float s = 0.f;
#pragma unroll
        for (int k = 0; k < 16; k++) {
            int idx = i + k * (WARM_BLOCKS * 256);
            if (idx < Nn * 16) {
                float4 v = x4[idx];
                s += v.x + v.y + v.z + v.w;
            }
        }
        if (s < -1e30f) d_sink = s;
    } else {
        int e = (b - WARM_BLOCKS) * 256 + threadIdx.x;
        if (e < Ee) atomicAdd(&d_counts[tgt[e]], 1);
    }
}

// Offset allocation, rows padded to 4 ints; seeds cursor = start.
__global__ void k_start() {
    int tid = threadIdx.x;
    int i = blockIdx.x * 1024 + tid;
    int v  = (i < Nn) ? d_counts[i] : 0;
    int vp = (v + 3) & ~3;
    int lane = tid & 31, wid = tid >> 5;
    int x = vp;
#pragma unroll
    for (int d = 1; d < 32; d <<= 1) {
        int t = __shfl_up_sync(0xffffffffu, x, d);
        if (lane >= d) x += t;
    }
    __shared__ int ws[32];
    __shared__ int sbase;
    if (lane == 31) ws[wid] = x;
    __syncthreads();
    if (wid == 0) {
        int y = ws[lane];
#pragma unroll
        for (int d = 1; d < 32; d <<= 1) {
            int t = __shfl_up_sync(0xffffffffu, y, d);
            if (lane >= d) y += t;
        }
        ws[lane] = y;
    }
    __syncthreads();
    if (tid == 0) sbase = atomicAdd(&d_gcnt, ws[31]);
    __syncthreads();
    int excl = x - vp + (wid ? ws[wid - 1] : 0);
    if (i < Nn) {
        int st = sbase + excl;
        d_start[i]  = st;
        d_cursor[i] = st;
        d_dinv[i]   = rsqrtf(1.0f + (float)v);
    }
}

__global__ void k_fill(const int* __restrict__ src, const int* __restrict__ tgt) {
    int e = blockIdx.x * blockDim.x + threadIdx.x;
    if (e >= Ee / 2) return;
    int e2 = e + Ee / 2;
    int t0 = tgt[e], t1 = tgt[e2];
    int p0 = atomicAdd(&d_cursor[t0], 1);
    int p1 = atomicAdd(&d_cursor[t1], 1);
    d_sorted[p0] = src[e];
    d_sorted[p1] = src[e2];
}

// ---------------- layer-1 GEMM: g[row] = fp16( dinv[row] * (x[row] @ W1) ) ----------------
__global__ void __launch_bounds__(128) k_gemm1(const float* __restrict__ xin) {
    __shared__ __half As[64 * ASTR];
    __shared__ __half Bs[64 * ASTR];
    int tid = threadIdx.x;
    int row0 = blockIdx.x * 64;
    const __half* wh = d_wh[0];

#pragma unroll
    for (int p = 0; p < 4; p++) {
        int idx = tid + p * 128;
        int r = idx >> 3, c8 = idx & 7;
        uint4 v = *(const uint4*)&wh[r * 64 + c8 * 8];
        *(uint4*)&Bs[r * ASTR + c8 * 8] = v;
    }
#pragma unroll
    for (int p = 0; p < 8; p++) {
        int idx = tid + p * 128;
        int r = idx >> 4, c4 = idx & 15;
        int row = row0 + r;
        float4 v = make_float4(0.f, 0.f, 0.f, 0.f);
        if (row < Nn) v = *(const float4*)&xin[row * 64 + c4 * 4];
        __half2 h0 = __floats2half2_rn(v.x, v.y);
        __half2 h1 = __floats2half2_rn(v.z, v.w);
        uint2 pk = make_uint2(reinterpret_cast<const unsigned&>(h0),
                              reinterpret_cast<const unsigned&>(h1));
        *(uint2*)&As[r * ASTR + c4 * 4] = pk;
    }
    __syncthreads();

    int warp = tid >> 5, lane = tid & 31;
    int mrow = warp * 16;

    uint32_t a[4][4];
#pragma unroll
    for (int kk = 0; kk < 4; kk++) {
        int r = mrow + (lane & 15);
        int cbyte = kk * 32 + (lane >> 4) * 16;
        uint32_t addr = (uint32_t)__cvta_generic_to_shared(&As[0]) + r * (ASTR * 2) + cbyte;
        asm volatile("ldmatrix.sync.aligned.m8n8.x4.shared.b16 {%0,%1,%2,%3}, [%4];"
                     : "=r"(a[kk][0]), "=r"(a[kk][1]), "=r"(a[kk][2]), "=r"(a[kk][3])
                     : "r"(addr));
    }

    int r0 = row0 + mrow + (lane >> 2);
    int r1 = r0 + 8;
    float dv0 = (r0 < Nn) ? d_dinv[r0] : 0.f;
    float dv1 = (r1 < Nn) ? d_dinv[r1] : 0.f;
    __half2* __restrict__ gout = d_gbuf[0];

#pragma unroll
    for (int n0 = 0; n0 < 64; n0 += 8) {
        float c0 = 0.f, c1 = 0.f, c2 = 0.f, c3 = 0.f;
#pragma unroll
        for (int kk = 0; kk < 4; kk++) {
            int krow = kk * 16 + (lane & 15);
            uint32_t addr = (uint32_t)__cvta_generic_to_shared(&Bs[0])
                          + krow * (ASTR * 2) + n0 * 2;
            uint32_t b0, b1;
            asm volatile("ldmatrix.sync.aligned.m8n8.x2.trans.shared.b16 {%0,%1}, [%2];"
                         : "=r"(b0), "=r"(b1) : "r"(addr));
            asm volatile("mma.sync.aligned.m16n8k16.row.col.f32.f16.f16.f32 "
                         "{%0,%1,%2,%3}, {%4,%5,%6,%7}, {%8,%9}, {%0,%1,%2,%3};"
                         : "+f"(c0), "+f"(c1), "+f"(c2), "+f"(c3)
                         : "r"(a[kk][0]), "r"(a[kk][1]), "r"(a[kk][2]), "r"(a[kk][3]),
                           "r"(b0), "r"(b1));
        }
        int cp = (n0 >> 1) + (lane & 3);
        if (r0 < Nn) {
            __half2 h = __floats2half2_rn(c0 * dv0, c1 * dv0);
            gout[r0 * 32 + cp] = h;
        }
        if (r1 < Nn) {
            __half2 h = __floats2half2_rn(c2 * dv1, c3 * dv1);
            gout[r1 * 32 + cp] = h;
        }
    }
}

// ---------------- agg gather core (shared by fused + pool kernels) ----------------
// Computes acc0..3 (8 fp32 features per 16-lane half-warp lane pair) for node t.
__device__ __forceinline__ void agg_gather(int t, int l16, const __half2* gin,
                                           float& acc0, float& acc1, float& acc2, float& acc3) {
    int base = d_start[t];
    int cnt  = d_counts[t];
    const uint2* __restrict__ g = (const uint2*)gin;
    {
        uint2 r = g[t * 16 + l16];
        float2 a = __half22float2(reinterpret_cast<const __half2&>(r.x));
        float2 b = __half22float2(reinterpret_cast<const __half2&>(r.y));
        acc0 = a.x; acc1 = a.y; acc2 = b.x; acc3 = b.y;
    }
    int i = 0;
    for (; i + 8 <= cnt; i += 8) {
        int4 ia = *(const int4*)&d_sorted[base + i];
        int4 ib = *(const int4*)&d_sorted[base + i + 4];
        uint2 r[8];
        r[0] = g[ia.x * 16 + l16];
        r[1] = g[ia.y * 16 + l16];
        r[2] = g[ia.z * 16 + l16];
        r[3] = g[ia.w * 16 + l16];
        r[4] = g[ib.x * 16 + l16];
        r[5] = g[ib.y * 16 + l16];
        r[6] = g[ib.z * 16 + l16];
        r[7] = g[ib.w * 16 + l16];
#pragma unroll
        for (int k = 0; k < 8; k++) {
            float2 a = __half22float2(reinterpret_cast<const __half2&>(r[k].x));
            float2 b = __half22float2(reinterpret_cast<const __half2&>(r[k].y));
            acc0 += a.x; acc1 += a.y; acc2 += b.x; acc3 += b.y;
        }
    }
    int rem = cnt - i;
    if (rem > 0) {
        int4 ia = *(const int4*)&d_sorted[base + i];
        int4 ib = *(const int4*)&d_sorted[base + i + 4];
        int s[8] = {ia.x, ia.y, ia.z, ia.w, ib.x, ib.y, ib.z, ib.w};
#pragma unroll
        for (int k = 0; k < 8; k++) {
            if (k < rem) {
                uint2 r = g[s[k] * 16 + l16];
                float2 a = __half22float2(reinterpret_cast<const __half2&>(r.x));
                float2 b = __half22float2(reinterpret_cast<const __half2&>(r.y));
                acc0 += a.x; acc1 += a.y; acc2 += b.x; acc3 += b.y;
            }
        }
    }
}

// ---------------- FUSED agg + next-layer GEMM ----------------
// Block = 16 contiguous nodes (one m16 tile). After gather: h = acc*dinv,
// tile = relu(h + bias) in fp16 smem; 8 warps do 16x64x64 mma with W[widx];
// write dinv-scaled fp16 messages to the other buffer.
__global__ void __launch_bounds__(256) k_aggg(int rd, int wr, int widx,
                                              const float* __restrict__ bias) {
    __shared__ __half Hs[16 * ASTR];
    __shared__ __half Bs[64 * ASTR];
    int tid  = threadIdx.x;
    int warp = tid >> 5, lane = tid & 31;
    int half = lane >> 4, l16 = lane & 15;
    int nl   = warp * 2 + half;                 // node-local 0..15
    int t    = blockIdx.x * 16 + nl;            // Nn % 16 == 0: always valid
    const __half* wh = d_wh[widx];

    // stage W (8KB) -- 512 uint4, 2 per thread
#pragma unroll
    for (int p = 0; p < 2; p++) {
        int idx = tid + p * 256;
        int r = idx >> 3, c8 = idx & 7;
        uint4 v = *(const uint4*)&wh[r * 64 + c8 * 8];
        *(uint4*)&Bs[r * ASTR + c8 * 8] = v;
    }

    float acc0, acc1, acc2, acc3;
    agg_gather(t, l16, d_gbuf[rd], acc0, acc1, acc2, acc3);
    float dv = d_dinv[t];

    // tile row = relu(h + bias), fp16
    float4 bv = *(const float4*)&bias[4 * l16];
    float v0 = fmaxf(acc0 * dv + bv.x, 0.f);
    float v1 = fmaxf(acc1 * dv + bv.y, 0.f);
    float v2 = fmaxf(acc2 * dv + bv.z, 0.f);
    float v3 = fmaxf(acc3 * dv + bv.w, 0.f);
    __half2 h0 = __floats2half2_rn(v0, v1);
    __half2 h1 = __floats2half2_rn(v2, v3);
    uint2 pk = make_uint2(reinterpret_cast<const unsigned&>(h0),
                          reinterpret_cast<const unsigned&>(h1));
    *(uint2*)&Hs[nl * ASTR + 4 * l16] = pk;
    __syncthreads();

    // mma: warp computes n-slice [8*warp, 8*warp+8)
    uint32_t a[4][4];
#pragma unroll
    for (int kk = 0; kk < 4; kk++) {
        int r = lane & 15;
        int cbyte = kk * 32 + (lane >> 4) * 16;
        uint32_t addr = (uint32_t)__cvta_generic_to_shared(&Hs[0]) + r * (ASTR * 2) + cbyte;
        asm volatile("ldmatrix.sync.aligned.m8n8.x4.shared.b16 {%0,%1,%2,%3}, [%4];"
                     : "=r"(a[kk][0]), "=r"(a[kk][1]), "=r"(a[kk][2]), "=r"(a[kk][3])
                     : "r"(addr));
    }
    int n0 = 8 * warp;
    float c0 = 0.f, c1 = 0.f, c2 = 0.f, c3 = 0.f;
#pragma unroll
    for (int kk = 0; kk < 4; kk++) {
        int krow = kk * 16 + (lane & 15);
        uint32_t addr = (uint32_t)__cvta_generic_to_shared(&Bs[0])
                      + krow * (ASTR * 2) + n0 * 2;
        uint32_t b0, b1;
        asm volatile("ldmatrix.sync.aligned.m8n8.x2.trans.shared.b16 {%0,%1}, [%2];"
                     : "=r"(b0), "=r"(b1) : "r"(addr));
        asm volatile("mma.sync.aligned.m16n8k16.row.col.f32.f16.f16.f32 "
                     "{%0,%1,%2,%3}, {%4,%5,%6,%7}, {%8,%9}, {%0,%1,%2,%3};"
                     : "+f"(c0), "+f"(c1), "+f"(c2), "+f"(c3)
                     : "r"(a[kk][0]), "r"(a[kk][1]), "r"(a[kk][2]), "r"(a[kk][3]),
                       "r"(b0), "r"(b1));
    }
    int r0 = blockIdx.x * 16 + (lane >> 2);
    int r1 = r0 + 8;
    float dv0 = d_dinv[r0];
    float dv1 = d_dinv[r1];
    int cp = 4 * warp + (lane & 3);
    __half2* __restrict__ gout = d_gbuf[wr];
    __half2 o0 = __floats2half2_rn(c0 * dv0, c1 * dv0);
    __half2 o1 = __floats2half2_rn(c2 * dv1, c3 * dv1);
    gout[r0 * 32 + cp] = o0;
    gout[r1 * 32 + cp] = o1;
}

// ---------------- final agg + mean-pool sum ----------------
__global__ void __launch_bounds__(256) k_aggp(int rd, const int* __restrict__ batch) {
    int tid  = threadIdx.x;
    int warp = tid >> 5, lane = tid & 31;
    int half = lane >> 4, l16 = lane & 15;
    int nl   = warp * 2 + half;
    int t    = blockIdx.x * 16 + nl;

    float acc0, acc1, acc2, acc3;
    agg_gather(t, l16, d_gbuf[rd], acc0, acc1, acc2, acc3);
    float dv = d_dinv[t];

    __shared__ float sm_h[16][64];
    __shared__ int   sm_bg[16];
    sm_h[nl][4 * l16 + 0] = acc0 * dv;
    sm_h[nl][4 * l16 + 1] = acc1 * dv;
    sm_h[nl][4 * l16 + 2] = acc2 * dv;
    sm_h[nl][4 * l16 + 3] = acc3 * dv;
    if (l16 == 0) sm_bg[nl] = batch[t];
    __syncthreads();
    if (tid < 64) {
        int f = tid;
        float acc = 0.f;
        int cur = sm_bg[0];
        for (int n = 0; n < 16; n++) {
            int bg = sm_bg[n];
            if (bg != cur) {
                atomicAdd(&d_psum[cur * 64 + f], acc);
                cur = bg; acc = 0.f;
            }
            acc += sm_h[n][f];
        }
        atomicAdd(&d_psum[cur * 64 + f], acc);
    }
}

// ---------------- head ----------------
__global__ void k_final(const int* __restrict__ batch,
                        const float* __restrict__ Wl, const float* __restrict__ bl,
                        const float* __restrict__ b4, float* __restrict__ out) {
    int tid = threadIdx.x;
    if (tid >= Gg * Cc) return;
    int gi = tid / Cc, c = tid % Cc;
    int lo = 0, hi = Nn;
    while (lo < hi) { int m = (lo + hi) >> 1; if (batch[m] < gi) lo = m + 1; else hi = m; }
    int lb = lo; lo = 0; hi = Nn;
    while (lo < hi) { int m = (lo + hi) >> 1; if (batch[m] < gi + 1) lo = m + 1; else hi = m; }
    int cnt = lo - lb;
    float inv = 1.0f / fmaxf((float)cnt, 1.0f);
    float acc = bl[c];
#pragma unroll 8
    for (int k = 0; k < 64; k++) {
        float pooled = d_psum[gi * 64 + k] * inv + b4[k];
        acc = fmaf(pooled, Wl[k * Cc + c], acc);
    }
    out[gi * Cc + c] = acc;
}

// ---------------- launch ----------------
extern "C" void kernel_launch(void* const* d_in, const int* in_sizes, int n_in,
                              void* d_out, int out_size) {
    const float* x     = (const float*)d_in[0];
    const int*   ei    = (const int*)d_in[1];
    const int*   batch = (const int*)d_in[2];
    const float* W1 = (const float*)d_in[3],  *b1 = (const float*)d_in[4];
    const float* W2 = (const float*)d_in[5],  *b2 = (const float*)d_in[6];
    const float* W3 = (const float*)d_in[7],  *b3 = (const float*)d_in[8];
    const float* W4 = (const float*)d_in[9],  *b4 = (const float*)d_in[10];
    const float* Wl = (const float*)d_in[11], *bl = (const float*)d_in[12];
    float* out = (float*)d_out;

    const int* src = ei;
    const int* tgt = ei + Ee;

    int gemm_grid = (Nn + 63) / 64;
    int agg_grid  = Nn / 16;                  // 6250, exact
    int edge_grid = (Ee + 255) / 256;

    k_init <<<(Nn + 255) / 256, 256>>>(W1, W2, W3, W4);
    k_count<<<WARM_BLOCKS + edge_grid, 256>>>(tgt, x);
    k_start<<<(Nn + 1023) / 1024, 1024>>>();
    k_gemm1<<<gemm_grid, 128>>>(x);
    k_fill <<<(Ee / 2 + 255) / 256, 256>>>(src, tgt);

    k_aggg<<<agg_grid, 256>>>(0, 1, 1, b1);   // h1 = agg(g1); g2 = gemm(relu(h1+b1), W2)
    k_aggg<<<agg_grid, 256>>>(1, 0, 2, b2);
    k_aggg<<<agg_grid, 256>>>(0, 1, 3, b3);
    k_aggp<<<agg_grid, 256>>>(1, batch);      // h4 agg + mean-pool sums

    k_final<<<1, Gg * Cc>>>(batch, Wl, bl, b4, out);
}

// round 17
// speedup vs baseline: 1.1604x; 1.0119x over previous
#include <cuda_runtime.h>
#include <cuda_fp16.h>
#include <cstdint>

#define Nn 100000
#define Ee 1600000
#define Hh 64
#define Cc 10
#define Gg 64
#define SORT_SZ (Ee + 3 * Nn + 64)
#define ASTR 72          // smem row stride in halves (conflict-free ldmatrix)
#define WARM_BLOCKS 391  // warm x into L2 under k_count's latency shadow
#define G1_BLOCKS 782    // gemm1 blocks (128 rows each) inside k_gfill
#define FILL_BLOCKS ((Ee / 2 + 255) / 256)

// ---------------- static device scratch (no allocations allowed) ----------------
__device__ int   d_counts[Nn];
__device__ int   d_cursor[Nn];
__device__ int   d_start[Nn];
__device__ float d_dinv[Nn];
__device__ __align__(16) int d_sorted[SORT_SZ];
__device__ __align__(16) __half2 d_gbuf[2][Nn * 32]; // double-buffered fp16 messages, 128B/row
__device__ __align__(16) __half d_wh[4][64 * 64];    // fp16 weights, k-major [k][n]
__device__ float d_psum[Gg * Hh];
__device__ float d_sink;
__device__ int   d_gcnt;

// ---------------- prep: zero + weight convert in one launch ----------------
__global__ void k_init(const float* __restrict__ W1, const float* __restrict__ W2,
                       const float* __restrict__ W3, const float* __restrict__ W4) {
    int i = blockIdx.x * blockDim.x + threadIdx.x;
    if (i < Nn) d_counts[i] = 0;
    if (i < Gg * Hh) d_psum[i] = 0.0f;
    if (i == 0) d_gcnt = 0;
    if (i < 4096) {
        d_wh[0][i] = __float2half(W1[i]);
        d_wh[1][i] = __float2half(W2[i]);
        d_wh[2][i] = __float2half(W3[i]);
        d_wh[3][i] = __float2half(W4[i]);
    }
}

// counting + x L2-warm in one grid
__global__ void k_count(const int* __restrict__ tgt, const float* __restrict__ x) {
    int b = blockIdx.x;
    if (b < WARM_BLOCKS) {
        const float4* __restrict__ x4 = (const float4*)x;
        int i = b * 256 + threadIdx.x;
        float s = 0.f;
#pragma unroll
        for (int k = 0; k < 16; k++) {
            int idx = i + k * (WARM_BLOCKS * 256);
            if (idx < Nn * 16) {
                float4 v = x4[idx];
                s += v.x + v.y + v.z + v.w;
            }
        }
        if (s < -1e30f) d_sink = s;
    } else {
        int e = (b - WARM_BLOCKS) * 256 + threadIdx.x;
        if (e < Ee) atomicAdd(&d_counts[tgt[e]], 1);
    }
}

// Offset allocation, rows padded to 4 ints; seeds cursor = start.
__global__ void k_start() {
    int tid = threadIdx.x;
    int i = blockIdx.x * 1024 + tid;
    int v  = (i < Nn) ? d_counts[i] : 0;
    int vp = (v + 3) & ~3;
    int lane = tid & 31, wid = tid >> 5;
    int x = vp;
#pragma unroll
    for (int d = 1; d < 32; d <<= 1) {
        int t = __shfl_up_sync(0xffffffffu, x, d);
        if (lane >= d) x += t;
    }
    __shared__ int ws[32];
    __shared__ int sbase;
    if (lane == 31) ws[wid] = x;
    __syncthreads();
    if (wid == 0) {
        int y = ws[lane];
#pragma unroll
        for (int d = 1; d < 32; d <<= 1) {
            int t = __shfl_up_sync(0xffffffffu, y, d);
            if (lane >= d) y += t;
        }
        ws[lane] = y;
    }
    __syncthreads();
    if (tid == 0) sbase = atomicAdd(&d_gcnt, ws[31]);
    __syncthreads();
    int excl = x - vp + (wid ? ws[wid - 1] : 0);
    if (i < Nn) {
        int st = sbase + excl;
        d_start[i]  = st;
        d_cursor[i] = st;
        d_dinv[i]   = rsqrtf(1.0f + (float)v);
    }
}

// ---------------- merged: layer-1 GEMM (blocks 0..G1-1) + CSR fill (rest) ----------------
// gemm part: 128 rows/block, 8 warps, warp-per-m16-tile; g1[row] = fp16(dinv*(x@W1))
// fill part: 2 independent atomic+store chains per thread
__global__ void __launch_bounds__(256) k_gfill(const float* __restrict__ xin,
                                               const int* __restrict__ src,
                                               const int* __restrict__ tgt) {
    __shared__ __half As[128 * ASTR];
    __shared__ __half Bs[64 * ASTR];
    int b = blockIdx.x;
    int tid = threadIdx.x;

    if (b >= G1_BLOCKS) {
        int e = (b - G1_BLOCKS) * 256 + tid;
        if (e < Ee / 2) {
            int e2 = e + Ee / 2;
            int t0 = tgt[e], t1 = tgt[e2];
            int p0 = atomicAdd(&d_cursor[t0], 1);
            int p1 = atomicAdd(&d_cursor[t1], 1);
            d_sorted[p0] = src[e];
            d_sorted[p1] = src[e2];
        }
        return;
    }

    int row0 = b * 128;
    const __half* wh = d_wh[0];

    // stage W: 512 uint4, 2 per thread
#pragma unroll
    for (int p = 0; p < 2; p++) {
        int idx = tid + p * 256;
        int r = idx >> 3, c8 = idx & 7;
        uint4 v = *(const uint4*)&wh[r * 64 + c8 * 8];
        *(uint4*)&Bs[r * ASTR + c8 * 8] = v;
    }
    // stage A: 128 rows x 16 float4 = 2048, 8 per thread; fp32->fp16
#pragma unroll
    for (int p = 0; p < 8; p++) {
        int idx = tid + p * 256;
        int r = idx >> 4, c4 = idx & 15;
        int row = row0 + r;
        float4 v = make_float4(0.f, 0.f, 0.f, 0.f);
        if (row < Nn) v = *(const float4*)&xin[row * 64 + c4 * 4];
        __half2 h0 = __floats2half2_rn(v.x, v.y);
        __half2 h1 = __floats2half2_rn(v.z, v.w);
        uint2 pk = make_uint2(reinterpret_cast<const unsigned&>(h0),
                              reinterpret_cast<const unsigned&>(h1));
        *(uint2*)&As[r * ASTR + c4 * 4] = pk;
    }
    __syncthreads();

    int warp = tid >> 5, lane = tid & 31;
    int mrow = warp * 16;

    uint32_t a[4][4];
#pragma unroll
    for (int kk = 0; kk < 4; kk++) {
        int r = mrow + (lane & 15);
        int cbyte = kk * 32 + (lane >> 4) * 16;
        uint32_t addr = (uint32_t)__cvta_generic_to_shared(&As[0]) + r * (ASTR * 2) + cbyte;
        asm volatile("ldmatrix.sync.aligned.m8n8.x4.shared.b16 {%0,%1,%2,%3}, [%4];"
                     : "=r"(a[kk][0]), "=r"(a[kk][1]), "=r"(a[kk][2]), "=r"(a[kk][3])
                     : "r"(addr));
    }

    int r0 = row0 + mrow + (lane >> 2);
    int r1 = r0 + 8;
    float dv0 = (r0 < Nn) ? d_dinv[r0] : 0.f;
    float dv1 = (r1 < Nn) ? d_dinv[r1] : 0.f;
    __half2* __restrict__ gout = d_gbuf[0];

#pragma unroll
    for (int n0 = 0; n0 < 64; n0 += 8) {
        float c0 = 0.f, c1 = 0.f, c2 = 0.f, c3 = 0.f;
#pragma unroll
        for (int kk = 0; kk < 4; kk++) {
            int krow = kk * 16 + (lane & 15);
            uint32_t addr = (uint32_t)__cvta_generic_to_shared(&Bs[0])
                          + krow * (ASTR * 2) + n0 * 2;
            uint32_t b0, b1;
            asm volatile("ldmatrix.sync.aligned.m8n8.x2.trans.shared.b16 {%0,%1}, [%2];"
                         : "=r"(b0), "=r"(b1) : "r"(addr));
            asm volatile("mma.sync.aligned.m16n8k16.row.col.f32.f16.f16.f32 "
                         "{%0,%1,%2,%3}, {%4,%5,%6,%7}, {%8,%9}, {%0,%1,%2,%3};"
                         : "+f"(c0), "+f"(c1), "+f"(c2), "+f"(c3)
                         : "r"(a[kk][0]), "r"(a[kk][1]), "r"(a[kk][2]), "r"(a[kk][3]),
                           "r"(b0), "r"(b1));
        }
        int cp = (n0 >> 1) + (lane & 3);
        if (r0 < Nn) {
            __half2 h = __floats2half2_rn(c0 * dv0, c1 * dv0);
            gout[r0 * 32 + cp] = h;
        }
        if (r1 < Nn) {
            __half2 h = __floats2half2_rn(c2 * dv1, c3 * dv1);
            gout[r1 * 32 + cp] = h;
        }
    }
}

// ---------------- agg gather core ----------------
__device__ __forceinline__ void agg_gather(int t, int l16, const __half2* gin,
                                           float& acc0, float& acc1, float& acc2, float& acc3) {
    int base = d_start[t];
    int cnt  = d_counts[t];
    const uint2* __restrict__ g = (const uint2*)gin;
    {
        uint2 r = g[t * 16 + l16];
        float2 a = __half22float2(reinterpret_cast<const __half2&>(r.x));
        float2 b = __half22float2(reinterpret_cast<const __half2&>(r.y));
        acc0 = a.x; acc1 = a.y; acc2 = b.x; acc3 = b.y;
    }
    int i = 0;
    for (; i + 8 <= cnt; i += 8) {
        int4 ia = *(const int4*)&d_sorted[base + i];
        int4 ib = *(const int4*)&d_sorted[base + i + 4];
        uint2 r[8];
        r[0] = g[ia.x * 16 + l16];
        r[1] = g[ia.y * 16 + l16];
        r[2] = g[ia.z * 16 + l16];
        r[3] = g[ia.w * 16 + l16];
        r[4] = g[ib.x * 16 + l16];
        r[5] = g[ib.y * 16 + l16];
        r[6] = g[ib.z * 16 + l16];
        r[7] = g[ib.w * 16 + l16];
#pragma unroll
        for (int k = 0; k < 8; k++) {
            float2 a = __half22float2(reinterpret_cast<const __half2&>(r[k].x));
            float2 b = __half22float2(reinterpret_cast<const __half2&>(r[k].y));
            acc0 += a.x; acc1 += a.y; acc2 += b.x; acc3 += b.y;
        }
    }
    int rem = cnt - i;
    if (rem > 0) {
        int4 ia = *(const int4*)&d_sorted[base + i];
        int4 ib = *(const int4*)&d_sorted[base + i + 4];
        int s[8] = {ia.x, ia.y, ia.z, ia.w, ib.x, ib.y, ib.z, ib.w};
#pragma unroll
        for (int k = 0; k < 8; k++) {
            if (k < rem) {
                uint2 r = g[s[k] * 16 + l16];
                float2 a = __half22float2(reinterpret_cast<const __half2&>(r.x));
                float2 b = __half22float2(reinterpret_cast<const __half2&>(r.y));
                acc0 += a.x; acc1 += a.y; acc2 += b.x; acc3 += b.y;
            }
        }
    }
}

// ---------------- FUSED agg + next-layer GEMM ----------------
__global__ void __launch_bounds__(256) k_aggg(int rd, int wr, int widx,
                                              const float* __restrict__ bias) {
    __shared__ __half Hs[16 * ASTR];
    __shared__ __half Bs[64 * ASTR];
    int tid  = threadIdx.x;
    int warp = tid >> 5, lane = tid & 31;
    int half = lane >> 4, l16 = lane & 15;
    int nl   = warp * 2 + half;
    int t    = blockIdx.x * 16 + nl;
    const __half* wh = d_wh[widx];

#pragma unroll
    for (int p = 0; p < 2; p++) {
        int idx = tid + p * 256;
        int r = idx >> 3, c8 = idx & 7;
        uint4 v = *(const uint4*)&wh[r * 64 + c8 * 8];
        *(uint4*)&Bs[r * ASTR + c8 * 8] = v;
    }

    float acc0, acc1, acc2, acc3;
    agg_gather(t, l16, d_gbuf[rd], acc0, acc1, acc2, acc3);
    float dv = d_dinv[t];

    float4 bv = *(const float4*)&bias[4 * l16];
    float v0 = fmaxf(acc0 * dv + bv.x, 0.f);
    float v1 = fmaxf(acc1 * dv + bv.y, 0.f);
    float v2 = fmaxf(acc2 * dv + bv.z, 0.f);
    float v3 = fmaxf(acc3 * dv + bv.w, 0.f);
    __half2 h0 = __floats2half2_rn(v0, v1);
    __half2 h1 = __floats2half2_rn(v2, v3);
    uint2 pk = make_uint2(reinterpret_cast<const unsigned&>(h0),
                          reinterpret_cast<const unsigned&>(h1));
    *(uint2*)&Hs[nl * ASTR + 4 * l16] = pk;
    __syncthreads();

    uint32_t a[4][4];
#pragma unroll
    for (int kk = 0; kk < 4; kk++) {
        int r = lane & 15;
        int cbyte = kk * 32 + (lane >> 4) * 16;
        uint32_t addr = (uint32_t)__cvta_generic_to_shared(&Hs[0]) + r * (ASTR * 2) + cbyte;
        asm volatile("ldmatrix.sync.aligned.m8n8.x4.shared.b16 {%0,%1,%2,%3}, [%4];"
                     : "=r"(a[kk][0]), "=r"(a[kk][1]), "=r"(a[kk][2]), "=r"(a[kk][3])
                     : "r"(addr));
    }
    int n0 = 8 * warp;
    float c0 = 0.f, c1 = 0.f, c2 = 0.f, c3 = 0.f;
#pragma unroll
    for (int kk = 0; kk < 4; kk++) {
        int krow = kk * 16 + (lane & 15);
        uint32_t addr = (uint32_t)__cvta_generic_to_shared(&Bs[0])
                      + krow * (ASTR * 2) + n0 * 2;
        uint32_t b0, b1;
        asm volatile("ldmatrix.sync.aligned.m8n8.x2.trans.shared.b16 {%0,%1}, [%2];"
                     : "=r"(b0), "=r"(b1) : "r"(addr));
        asm volatile("mma.sync.aligned.m16n8k16.row.col.f32.f16.f16.f32 "
                     "{%0,%1,%2,%3}, {%4,%5,%6,%7}, {%8,%9}, {%0,%1,%2,%3};"
                     : "+f"(c0), "+f"(c1), "+f"(c2), "+f"(c3)
                     : "r"(a[kk][0]), "r"(a[kk][1]), "r"(a[kk][2]), "r"(a[kk][3]),
                       "r"(b0), "r"(b1));
    }
    int r0 = blockIdx.x * 16 + (lane >> 2);
    int r1 = r0 + 8;
    float dv0 = d_dinv[r0];
    float dv1 = d_dinv[r1];
    int cp = 4 * warp + (lane & 3);
    __half2* __restrict__ gout = d_gbuf[wr];
    __half2 o0 = __floats2half2_rn(c0 * dv0, c1 * dv0);
    __half2 o1 = __floats2half2_rn(c2 * dv1, c3 * dv1);
    gout[r0 * 32 + cp] = o0;
    gout[r1 * 32 + cp] = o1;
}

// ---------------- final agg + mean-pool sum ----------------
__global__ void __launch_bounds__(256) k_aggp(int rd, const int* __restrict__ batch) {
    int tid  = threadIdx.x;
    int warp = tid >> 5, lane = tid & 31;
    int half = lane >> 4, l16 = lane & 15;
    int nl   = warp * 2 + half;
    int t    = blockIdx.x * 16 + nl;

    float acc0, acc1, acc2, acc3;
    agg_gather(t, l16, d_gbuf[rd], acc0, acc1, acc2, acc3);
    float dv = d_dinv[t];

    __shared__ float sm_h[16][64];
    __shared__ int   sm_bg[16];
    sm_h[nl][4 * l16 + 0] = acc0 * dv;
    sm_h[nl][4 * l16 + 1] = acc1 * dv;
    sm_h[nl][4 * l16 + 2] = acc2 * dv;
    sm_h[nl][4 * l16 + 3] = acc3 * dv;
    if (l16 == 0) sm_bg[nl] = batch[t];
    __syncthreads();
    if (tid < 64) {
        int f = tid;
        float acc = 0.f;
        int cur = sm_bg[0];
        for (int n = 0; n < 16; n++) {
            int bg = sm_bg[n];
            if (bg != cur) {
                atomicAdd(&d_psum[cur * 64 + f], acc);
                cur = bg; acc = 0.f;
            }
            acc += sm_h[n][f];
        }
        atomicAdd(&d_psum[cur * 64 + f], acc);
    }
}

// ---------------- head ----------------
__global__ void k_final(const int* __restrict__ batch,
                        const float* __restrict__ Wl, const float* __restrict__ bl,
                        const float* __restrict__ b4, float* __restrict__ out) {
    int tid = threadIdx.x;
    if (tid >= Gg * Cc) return;
    int gi = tid / Cc, c = tid % Cc;
    int lo = 0, hi = Nn;
    while (lo < hi) { int m = (lo + hi) >> 1; if (batch[m] < gi) lo = m + 1; else hi = m; }
    int lb = lo; lo = 0; hi = Nn;
    while (lo < hi) { int m = (lo + hi) >> 1; if (batch[m] < gi + 1) lo = m + 1; else hi = m; }
    int cnt = lo - lb;
    float inv = 1.0f / fmaxf((float)cnt, 1.0f);
    float acc = bl[c];
#pragma unroll 8
    for (int k = 0; k < 64; k++) {
        float pooled = d_psum[gi * 64 + k] * inv + b4[k];
        acc = fmaf(pooled, Wl[k * Cc + c], acc);
    }
    out[gi * Cc + c] = acc;
}

// ---------------- launch ----------------
extern "C" void kernel_launch(void* const* d_in, const int* in_sizes, int n_in,
                              void* d_out, int out_size) {
    const float* x     = (const float*)d_in[0];
    const int*   ei    = (const int*)d_in[1];
    const int*   batch = (const int*)d_in[2];
    const float* W1 = (const float*)d_in[3],  *b1 = (const float*)d_in[4];
    const float* W2 = (const float*)d_in[5],  *b2 = (const float*)d_in[6];
    const float* W3 = (const float*)d_in[7],  *b3 = (const float*)d_in[8];
    const float* W4 = (const float*)d_in[9],  *b4 = (const float*)d_in[10];
    const float* Wl = (const float*)d_in[11], *bl = (const float*)d_in[12];
    float* out = (float*)d_out;

    const int* src = ei;
    const int* tgt = ei + Ee;

    int agg_grid  = Nn / 16;                  // 6250, exact
    int edge_grid = (Ee + 255) / 256;

    k_init <<<(Nn + 255) / 256, 256>>>(W1, W2, W3, W4);
    k_count<<<WARM_BLOCKS + edge_grid, 256>>>(tgt, x);
    k_start<<<(Nn + 1023) / 1024, 1024>>>();
    k_gfill<<<G1_BLOCKS + FILL_BLOCKS, 256>>>(x, src, tgt);   // gemm1 hidden under fill

    k_aggg<<<agg_grid, 256>>>(0, 1, 1, b1);
    k_aggg<<<agg_grid, 256>>>(1, 0, 2, b2);
    k_aggg<<<agg_grid, 256>>>(0, 1, 3, b3);
    k_aggp<<<agg_grid, 256>>>(1, batch);

    k_final<<<1, Gg * Cc>>>(batch, Wl, bl, b4, out);
}